// round 12
// baseline (speedup 1.0000x reference)
#include <cuda_runtime.h>
#include <math.h>
#include <stdint.h>

#define BATCH 1024
#define FEAT  512
#define NT    64
#define CSETN 64
#define DDIM  1024

// Output layout (floats): A_real, A_imag, D_real_n, D_imag_n, CSet
#define OFF_AR 0L
#define OFF_AI 4194304L
#define OFF_DR 8388608L
#define OFF_DI 9437184L
#define OFF_CS 10485760L

__device__ float g_cs[BATCH * NT];
__device__ float g_sn[BATCH * NT];

__device__ __forceinline__ uint32_t f2tf32(float f) {
    uint32_t r;
    asm("cvt.rna.tf32.f32 %0, %1;" : "=r"(r) : "f"(f));
    return r;
}

__device__ __forceinline__ void mma_tf32(float* d, const uint32_t* a, const uint32_t* b) {
    asm volatile(
        "mma.sync.aligned.m16n8k8.row.col.f32.tf32.tf32.f32 "
        "{%0,%1,%2,%3}, {%4,%5,%6,%7}, {%8,%9}, {%0,%1,%2,%3};"
        : "+f"(d[0]), "+f"(d[1]), "+f"(d[2]), "+f"(d[3])
        : "r"(a[0]), "r"(a[1]), "r"(a[2]), "r"(a[3]), "r"(b[0]), "r"(b[1]));
}

// ---------------------------------------------------------------------------
// Fused tf32 GEMM + normalization, ks-split. 512 CTAs x 128 threads.
// CTA: 64 batch rows x (32 Dr + 32 Di cols = 64 B smem rows).
//   B smem rows 0..31 = W_Dr[n0..n0+31], rows 32..63 = W_Di[n0..n0+31].
// 4 warps: warpM in {0,1} -> 32-row slice; warpN in {0,1} -> which ks
// sub-step (k%16 in [0,8) vs [8,16)) of every k-tile. Each warp's tile is
// 32 rows x 64 B-rows (1.5 LDS.32 per MMA, same as the best R10 config).
// End: one smem exchange adds warpN=1 partials into warpN=0, which then
// does the warp-local normalization epilogue.
// ---------------------------------------------------------------------------
__global__ __launch_bounds__(128, 4)
void dgemm_kernel(const float* __restrict__ x,
                  const float* __restrict__ Wr, const float* __restrict__ br,
                  const float* __restrict__ Wi, const float* __restrict__ bi,
                  float* __restrict__ out)
{
    constexpr int LDK = 20;
    constexpr int BK  = 16;
    constexpr int NKT = FEAT / BK;   // 32
    constexpr int LDR = 66;

    __shared__ union {
        struct { uint32_t As[2][64 * LDK]; uint32_t Bs[2][64 * LDK]; } g;
        float red[64][LDR];
    } sm;

    const int tid   = threadIdx.x;
    const int lane  = tid & 31;
    const int warp  = tid >> 5;
    const int g     = lane >> 2;
    const int t4    = lane & 3;
    const int bx    = blockIdx.x;

    const int warpM = warp & 1;
    const int warpN = warp >> 1;       // ks sub-step owner

    const int mBase = (bx >> 5) * 64;
    const int n0    = (bx & 31) * 32;

    float* Cr = out + OFF_DR;
    float* Ci = out + OFF_DI;

    float d[2][8][4];
#pragma unroll
    for (int i = 0; i < 2; i++)
#pragma unroll
        for (int j = 0; j < 8; j++)
#pragma unroll
            for (int v = 0; v < 4; v++) d[i][j][v] = 0.0f;

    // Loaders: A tile 64x16 = 256 float4 (2/thread); B tile same.
    float4 pa[2], pb[2];
    const float* aptr[2];
    const float* bptr[2];
    int srow[2], skq[2];
#pragma unroll
    for (int t = 0; t < 2; t++) {
        int ti  = tid + 128 * t;
        int row = ti >> 2;           // 0..63
        int kq4 = (ti & 3) * 4;
        srow[t] = row; skq[t] = kq4;
        aptr[t] = &x[(size_t)(mBase + row) * FEAT + kq4];
        const float* src = (row < 32) ? &Wr[(size_t)(n0 + row) * FEAT]
                                      : &Wi[(size_t)(n0 + row - 32) * FEAT];
        bptr[t] = &src[kq4];
    }

#define LOADG(kt)                                                              \
    do {                                                                       \
        _Pragma("unroll")                                                      \
        for (int t = 0; t < 2; t++) {                                          \
            pa[t] = *reinterpret_cast<const float4*>(aptr[t] + (kt) * BK);     \
            pb[t] = *reinterpret_cast<const float4*>(bptr[t] + (kt) * BK);     \
        }                                                                      \
    } while (0)

#define STS(bf)                                                                \
    do {                                                                       \
        _Pragma("unroll")                                                      \
        for (int t = 0; t < 2; t++) {                                          \
            *reinterpret_cast<uint4*>(&sm.g.As[bf][srow[t] * LDK + skq[t]]) =  \
                make_uint4(f2tf32(pa[t].x), f2tf32(pa[t].y),                   \
                           f2tf32(pa[t].z), f2tf32(pa[t].w));                  \
            *reinterpret_cast<uint4*>(&sm.g.Bs[bf][srow[t] * LDK + skq[t]]) =  \
                make_uint4(f2tf32(pb[t].x), f2tf32(pb[t].y),                   \
                           f2tf32(pb[t].z), f2tf32(pb[t].w));                  \
        }                                                                      \
    } while (0)

    LOADG(0);
    STS(0);
    __syncthreads();

    const int kb = warpN * 8 + t4;     // this warp's k-sub-step slot

    int buf = 0;
    for (int kt = 0; kt < NKT; kt++) {
        if (kt < NKT - 1) LOADG(kt + 1);

        const uint32_t* as = sm.g.As[buf];
        const uint32_t* bs = sm.g.Bs[buf];

        uint32_t af[2][4];
#pragma unroll
        for (int mi = 0; mi < 2; mi++) {
            const int r0 = (warpM * 32 + mi * 16 + g) * LDK;
            af[mi][0] = as[r0 + kb];
            af[mi][1] = as[r0 + 8 * LDK + kb];
            af[mi][2] = as[r0 + kb + 4];
            af[mi][3] = as[r0 + 8 * LDK + kb + 4];
        }
        uint32_t bq[8][2];
#pragma unroll
        for (int nj = 0; nj < 8; nj++) {
            const int rb = (nj * 8 + g) * LDK;
            bq[nj][0] = bs[rb + kb];
            bq[nj][1] = bs[rb + kb + 4];
        }
#pragma unroll
        for (int mi = 0; mi < 2; mi++)
#pragma unroll
            for (int nj = 0; nj < 8; nj++)
                mma_tf32(d[mi][nj], af[mi], bq[nj]);

        if (kt < NKT - 1) {
            STS(buf ^ 1);
            __syncthreads();
            buf ^= 1;
        }
    }
#undef LOADG
#undef STS

    // ---------- ks-split reduction: warpN=1 -> smem -> warpN=0 ----------
    __syncthreads();
    if (warpN == 1) {
#pragma unroll
        for (int mi = 0; mi < 2; mi++)
#pragma unroll
            for (int rv = 0; rv < 2; rv++) {
                const int row = warpM * 32 + mi * 16 + g + 8 * rv;
#pragma unroll
                for (int nj = 0; nj < 8; nj++) {
                    const int col = nj * 8 + 2 * t4;
                    sm.red[row][col]     = d[mi][nj][rv * 2 + 0];
                    sm.red[row][col + 1] = d[mi][nj][rv * 2 + 1];
                }
            }
    }
    __syncthreads();

    if (warpN == 0) {
#pragma unroll
        for (int mi = 0; mi < 2; mi++)
#pragma unroll
            for (int rv = 0; rv < 2; rv++) {
                const int row = warpM * 32 + mi * 16 + g + 8 * rv;
#pragma unroll
                for (int nj = 0; nj < 8; nj++) {
                    const int col = nj * 8 + 2 * t4;
                    d[mi][nj][rv * 2 + 0] += sm.red[row][col];
                    d[mi][nj][rv * 2 + 1] += sm.red[row][col + 1];
                }
            }

        // ---------- Epilogue: bias + warp-local normalization ----------
#pragma unroll
        for (int nj = 0; nj < 8; nj++) {
            const int col = n0 + (nj & 3) * 8 + 2 * t4;
            const float* bsrc = (nj < 4) ? br : bi;
            float bxv = bsrc[col];
            float byv = bsrc[col + 1];
#pragma unroll
            for (int mi = 0; mi < 2; mi++) {
                d[mi][nj][0] += bxv; d[mi][nj][1] += byv;
                d[mi][nj][2] += bxv; d[mi][nj][3] += byv;
            }
        }

#pragma unroll
        for (int mi = 0; mi < 2; mi++) {
            float s[2][2];
#pragma unroll
            for (int rv = 0; rv < 2; rv++)
#pragma unroll
                for (int p = 0; p < 2; p++) s[rv][p] = 0.0f;

#pragma unroll
            for (int nj = 0; nj < 8; nj++) {
                int p = (nj & 3) >> 1;
                s[0][p] += d[mi][nj][0] * d[mi][nj][0] + d[mi][nj][1] * d[mi][nj][1];
                s[1][p] += d[mi][nj][2] * d[mi][nj][2] + d[mi][nj][3] * d[mi][nj][3];
            }
#pragma unroll
            for (int rv = 0; rv < 2; rv++)
#pragma unroll
                for (int p = 0; p < 2; p++) {
                    float v = s[rv][p];
                    v += __shfl_xor_sync(0xffffffffu, v, 1);
                    v += __shfl_xor_sync(0xffffffffu, v, 2);
                    s[rv][p] = 2.0f * rsqrtf(8.0f * v);
                }

#pragma unroll
            for (int rv = 0; rv < 2; rv++) {
                const int grow = mBase + warpM * 32 + mi * 16 + g + 8 * rv;
#pragma unroll
                for (int nj = 0; nj < 8; nj++) {
                    const int p   = (nj & 3) >> 1;
                    const int col = n0 + (nj & 3) * 8 + 2 * t4;
                    float sc = s[rv][p];
                    float v0 = d[mi][nj][rv * 2 + 0] * sc;
                    float v1 = d[mi][nj][rv * 2 + 1] * sc;
                    float* C = (nj < 4) ? Cr : Ci;
                    *reinterpret_cast<float2*>(&C[(size_t)grow * DDIM + col]) =
                        make_float2(v0, v1);
                }
            }
        }
    }
}

// ---------------------------------------------------------------------------
// theta SGEMM: cs/sn = cos/sin(x @ W_A^T + b_A). SIMT, 64 CTAs x 256 thr.
// ---------------------------------------------------------------------------
template <int BM, int BN, int BK, int TM, int TN>
__global__ __launch_bounds__((BM / TM) * (BN / TN))
void theta_kernel(const float* __restrict__ A,
                  const float* __restrict__ W, const float* __restrict__ bias,
                  float* __restrict__ Ccs, float* __restrict__ Csn)
{
    constexpr int NTH = (BM / TM) * (BN / TN);
    __shared__ float As[BK][BM + 4];
    __shared__ float Bs[BK][BN + 4];

    const int tid  = threadIdx.x;
    const int tcol = tid % (BN / TN);
    const int trow = tid / (BN / TN);
    const int mBase = blockIdx.x * BM;

    float acc[TM][TN];
#pragma unroll
    for (int i = 0; i < TM; i++)
#pragma unroll
        for (int j = 0; j < TN; j++) acc[i][j] = 0.0f;

    for (int k0 = 0; k0 < FEAT; k0 += BK) {
        for (int i = tid; i < BM * BK / 4; i += NTH) {
            int r  = i / (BK / 4);
            int kc = (i % (BK / 4)) * 4;
            float4 v = *reinterpret_cast<const float4*>(
                &A[(size_t)(mBase + r) * FEAT + k0 + kc]);
            As[kc + 0][r] = v.x; As[kc + 1][r] = v.y;
            As[kc + 2][r] = v.z; As[kc + 3][r] = v.w;
        }
        for (int i = tid; i < BN * BK / 4; i += NTH) {
            int r  = i / (BK / 4);
            int kc = (i % (BK / 4)) * 4;
            float4 v = *reinterpret_cast<const float4*>(
                &W[(size_t)r * FEAT + k0 + kc]);
            Bs[kc + 0][r] = v.x; Bs[kc + 1][r] = v.y;
            Bs[kc + 2][r] = v.z; Bs[kc + 3][r] = v.w;
        }
        __syncthreads();

#pragma unroll
        for (int k = 0; k < BK; k++) {
            float am[TM], bn[TN];
#pragma unroll
            for (int i = 0; i < TM; i++) am[i] = As[k][trow * TM + i];
#pragma unroll
            for (int j = 0; j < TN; j++) bn[j] = Bs[k][tcol * TN + j];
#pragma unroll
            for (int i = 0; i < TM; i++)
#pragma unroll
                for (int j = 0; j < TN; j++) acc[i][j] += am[i] * bn[j];
        }
        __syncthreads();
    }

    const int col = tcol * TN;
#pragma unroll
    for (int i = 0; i < TM; i++) {
        int row = mBase + trow * TM + i;
#pragma unroll
        for (int j = 0; j < TN; j++) {
            float th = acc[i][j] + bias[col + j];
            float s, c;
            sincosf(th, &s, &c);
            Ccs[(size_t)row * NT + col + j] = c;
            Csn[(size_t)row * NT + col + j] = s;
        }
    }
}

// ---------------------------------------------------------------------------
// A_real / A_imag zeros + diag fill (1 thread per float4 slot); tail = CSet.
// ---------------------------------------------------------------------------
__global__ __launch_bounds__(256)
void afill_kernel(const float* __restrict__ cs, const float* __restrict__ sn,
                  const float* __restrict__ csrc, float* __restrict__ out)
{
    int idx = blockIdx.x * blockDim.x + threadIdx.x;
    if (idx < BATCH * NT * 16) {
        int q = idx & 15;
        int t = (idx >> 4) & 63;
        int b = idx >> 10;

        float4 zr = make_float4(0.f, 0.f, 0.f, 0.f);
        float4 zi = make_float4(0.f, 0.f, 0.f, 0.f);
        if (q == (t >> 2)) {
            reinterpret_cast<float*>(&zr)[t & 3] = cs[b * NT + t];
            reinterpret_cast<float*>(&zi)[t & 3] = sn[b * NT + t];
        }
        reinterpret_cast<float4*>(out + OFF_AR)[idx] = zr;
        reinterpret_cast<float4*>(out + OFF_AI)[idx] = zi;
    } else {
        int c = idx - BATCH * NT * 16;
        if (c < CSETN * NT) {
            reinterpret_cast<float4*>(out + OFF_CS)[c] =
                reinterpret_cast<const float4*>(csrc)[c];
        }
    }
}

extern "C" void kernel_launch(void* const* d_in, const int* in_sizes, int n_in,
                              void* d_out, int out_size)
{
    const float* x    = (const float*)d_in[0];
    const float* W_A  = (const float*)d_in[1];
    const float* b_A  = (const float*)d_in[2];
    const float* W_Dr = (const float*)d_in[3];
    const float* b_Dr = (const float*)d_in[4];
    const float* W_Di = (const float*)d_in[5];
    const float* b_Di = (const float*)d_in[6];
    const float* CSet = (const float*)d_in[7];
    float* out = (float*)d_out;

    float *cs = nullptr, *sn = nullptr;
    cudaGetSymbolAddress((void**)&cs, g_cs);
    cudaGetSymbolAddress((void**)&sn, g_sn);

    static cudaStream_t s2 = nullptr;
    static cudaEvent_t evFork = nullptr, evJoin = nullptr;
    static bool init_tried = false;
    if (!init_tried) {
        init_tried = true;
        if (cudaStreamCreateWithFlags(&s2, cudaStreamNonBlocking) != cudaSuccess)
            s2 = nullptr;
        if (s2) {
            if (cudaEventCreateWithFlags(&evFork, cudaEventDisableTiming) != cudaSuccess ||
                cudaEventCreateWithFlags(&evJoin, cudaEventDisableTiming) != cudaSuccess) {
                evFork = evJoin = nullptr;
            }
        }
    }
    const bool forked = (s2 && evFork && evJoin);

    if (forked) {
        cudaEventRecord(evFork, 0);
        cudaStreamWaitEvent(s2, evFork, 0);
    }

    // Branch A (default stream): D GEMM + fused normalization (ks-split)
    dgemm_kernel<<<512, 128>>>(x, W_Dr, b_Dr, W_Di, b_Di, out);

    // Branch B: theta (cos/sin) -> A planes + CSet
    {
        cudaStream_t sb = forked ? s2 : (cudaStream_t)0;
        theta_kernel<16, 64, 16, 1, 4><<<BATCH / 16, 256, 0, sb>>>(
            x, W_A, b_A, cs, sn);
        int total = BATCH * NT * 16 + CSETN * NT;
        afill_kernel<<<(total + 255) / 256, 256, 0, sb>>>(cs, sn, CSet, out);
        if (forked) {
            cudaEventRecord(evJoin, s2);
            cudaStreamWaitEvent(0, evJoin, 0);
        }
    }
}

// round 14
// speedup vs baseline: 1.3694x; 1.3694x over previous
#include <cuda_runtime.h>
#include <math.h>
#include <stdint.h>

#define BATCH 1024
#define FEAT  512
#define NT    64
#define CSETN 64
#define DDIM  1024

// Output layout (floats): A_real, A_imag, D_real_n, D_imag_n, CSet
#define OFF_AR 0L
#define OFF_AI 4194304L
#define OFF_DR 8388608L
#define OFF_DI 9437184L
#define OFF_CS 10485760L

__device__ float g_cs[BATCH * NT];
__device__ float g_sn[BATCH * NT];

__device__ __forceinline__ uint32_t f2tf32(float f) {
    uint32_t r;
    asm("cvt.rna.tf32.f32 %0, %1;" : "=r"(r) : "f"(f));
    return r;
}

__device__ __forceinline__ void mma_tf32(float* d, const uint32_t* a, const uint32_t* b) {
    asm volatile(
        "mma.sync.aligned.m16n8k8.row.col.f32.tf32.tf32.f32 "
        "{%0,%1,%2,%3}, {%4,%5,%6,%7}, {%8,%9}, {%0,%1,%2,%3};"
        : "+f"(d[0]), "+f"(d[1]), "+f"(d[2]), "+f"(d[3])
        : "r"(a[0]), "r"(a[1]), "r"(a[2]), "r"(a[3]), "r"(b[0]), "r"(b[1]));
}

// ---------------------------------------------------------------------------
// Fused tf32 GEMM + normalization. 256 CTAs x 128 threads (R10 config).
// CTA: 128 batch rows x (32 Dr + 32 Di cols = 64 B smem rows).
// 4 warps, warp tile 32 rows x 64 B-rows (1.5 LDS/MMA ratio).
// k-PERMUTED smem layout: word (row,k) lives at
//   row*20 + (k&3)*2 + ((k>>2)&1) + ((k>>3)*8)
// so (k, k+4) are adjacent -> every fragment load is one conflict-free
// LDS.64 (addresses 20g+2*t4 cover all even banks exactly once).
// ---------------------------------------------------------------------------
__global__ __launch_bounds__(128, 3)
void dgemm_kernel(const float* __restrict__ x,
                  const float* __restrict__ Wr, const float* __restrict__ br,
                  const float* __restrict__ Wi, const float* __restrict__ bi,
                  float* __restrict__ out)
{
    constexpr int LDK = 20;
    constexpr int BK  = 16;
    constexpr int NKT = FEAT / BK;   // 32

    __shared__ uint32_t As[2][128 * LDK];
    __shared__ uint32_t Bs[2][64 * LDK];

    const int tid   = threadIdx.x;
    const int lane  = tid & 31;
    const int warp  = tid >> 5;
    const int g     = lane >> 2;
    const int t4    = lane & 3;
    const int bx    = blockIdx.x;

    const int mBase = (bx >> 5) * 128;
    const int n0    = (bx & 31) * 32;

    float* Cr = out + OFF_DR;
    float* Ci = out + OFF_DI;

    float d[2][8][4];
#pragma unroll
    for (int i = 0; i < 2; i++)
#pragma unroll
        for (int j = 0; j < 8; j++)
#pragma unroll
            for (int v = 0; v < 4; v++) d[i][j][v] = 0.0f;

    // Loaders: A tile 128x16 = 512 float4 (4/thread); B tile 64x16 (2/thread)
    float4 pa[4], pb[2];
    int arow[4], abase[4], brow[2], bbase[2];
    const float* aptr[4];
    const float* bptr[2];
#pragma unroll
    for (int t = 0; t < 4; t++) {
        int ti  = tid + 128 * t;
        int row = ti >> 2;              // 0..127
        int kq  = ti & 3;               // float4 index within k-tile
        arow[t]  = row;
        abase[t] = row * LDK + (kq & 1) + ((kq >> 1) << 3);
        aptr[t]  = &x[(size_t)(mBase + row) * FEAT + kq * 4];
    }
#pragma unroll
    for (int t = 0; t < 2; t++) {
        int ti  = tid + 128 * t;
        int row = ti >> 2;              // 0..63
        int kq  = ti & 3;
        brow[t]  = row;
        bbase[t] = row * LDK + (kq & 1) + ((kq >> 1) << 3);
        const float* src = (row < 32) ? &Wr[(size_t)(n0 + row) * FEAT]
                                      : &Wi[(size_t)(n0 + row - 32) * FEAT];
        bptr[t] = &src[kq * 4];
    }

#define LOADG(kt)                                                              \
    do {                                                                       \
        _Pragma("unroll")                                                      \
        for (int t = 0; t < 4; t++)                                            \
            pa[t] = *reinterpret_cast<const float4*>(aptr[t] + (kt) * BK);     \
        _Pragma("unroll")                                                      \
        for (int t = 0; t < 2; t++)                                            \
            pb[t] = *reinterpret_cast<const float4*>(bptr[t] + (kt) * BK);     \
    } while (0)

    // permuted scatter: float4 components j=0..3 go to base + 2*j
#define STS(bf)                                                                \
    do {                                                                       \
        _Pragma("unroll")                                                      \
        for (int t = 0; t < 4; t++) {                                          \
            As[bf][abase[t] + 0] = f2tf32(pa[t].x);                            \
            As[bf][abase[t] + 2] = f2tf32(pa[t].y);                            \
            As[bf][abase[t] + 4] = f2tf32(pa[t].z);                            \
            As[bf][abase[t] + 6] = f2tf32(pa[t].w);                            \
        }                                                                      \
        _Pragma("unroll")                                                      \
        for (int t = 0; t < 2; t++) {                                          \
            Bs[bf][bbase[t] + 0] = f2tf32(pb[t].x);                            \
            Bs[bf][bbase[t] + 2] = f2tf32(pb[t].y);                            \
            Bs[bf][bbase[t] + 4] = f2tf32(pb[t].z);                            \
            Bs[bf][bbase[t] + 6] = f2tf32(pb[t].w);                            \
        }                                                                      \
    } while (0)

    LOADG(0);
    STS(0);
    __syncthreads();

    const int arow0 = (warp * 32 + g) * LDK;        // mi stride 16*LDK
    const int frag  = t4 * 2;                       // +ks*8

    int buf = 0;
    for (int kt = 0; kt < NKT; kt++) {
        if (kt < NKT - 1) LOADG(kt + 1);

        const uint32_t* as = As[buf];
        const uint32_t* bs = Bs[buf];
#pragma unroll
        for (int ks = 0; ks < 2; ks++) {
            const int fb = frag + ks * 8;
            uint32_t af[2][4];
#pragma unroll
            for (int mi = 0; mi < 2; mi++) {
                uint2 lo = *reinterpret_cast<const uint2*>(
                    &as[arow0 + mi * 16 * LDK + fb]);
                uint2 hi = *reinterpret_cast<const uint2*>(
                    &as[arow0 + (mi * 16 + 8) * LDK + fb]);
                af[mi][0] = lo.x; af[mi][1] = hi.x;
                af[mi][2] = lo.y; af[mi][3] = hi.y;
            }
            uint32_t bq[8][2];
#pragma unroll
            for (int nj = 0; nj < 8; nj++) {
                uint2 v = *reinterpret_cast<const uint2*>(
                    &bs[(nj * 8 + g) * LDK + fb]);
                bq[nj][0] = v.x; bq[nj][1] = v.y;
            }
#pragma unroll
            for (int mi = 0; mi < 2; mi++)
#pragma unroll
                for (int nj = 0; nj < 8; nj++)
                    mma_tf32(d[mi][nj], af[mi], bq[nj]);
        }

        if (kt < NKT - 1) {
            STS(buf ^ 1);
            __syncthreads();
            buf ^= 1;
        }
    }
#undef LOADG
#undef STS

    // ---------- Epilogue: bias + warp-local normalization (R10, proven) ----
    const int warpM = warp;   // 4 warps each own 32 rows
#pragma unroll
    for (int nj = 0; nj < 8; nj++) {
        const int col = n0 + (nj & 3) * 8 + 2 * t4;
        const float* bsrc = (nj < 4) ? br : bi;
        float bxv = bsrc[col];
        float byv = bsrc[col + 1];
#pragma unroll
        for (int mi = 0; mi < 2; mi++) {
            d[mi][nj][0] += bxv; d[mi][nj][1] += byv;
            d[mi][nj][2] += bxv; d[mi][nj][3] += byv;
        }
    }

#pragma unroll
    for (int mi = 0; mi < 2; mi++) {
        float s[2][2];
#pragma unroll
        for (int rv = 0; rv < 2; rv++)
#pragma unroll
            for (int p = 0; p < 2; p++) s[rv][p] = 0.0f;

#pragma unroll
        for (int nj = 0; nj < 8; nj++) {
            int p = (nj & 3) >> 1;
            s[0][p] += d[mi][nj][0] * d[mi][nj][0] + d[mi][nj][1] * d[mi][nj][1];
            s[1][p] += d[mi][nj][2] * d[mi][nj][2] + d[mi][nj][3] * d[mi][nj][3];
        }
#pragma unroll
        for (int rv = 0; rv < 2; rv++)
#pragma unroll
            for (int p = 0; p < 2; p++) {
                float v = s[rv][p];
                v += __shfl_xor_sync(0xffffffffu, v, 1);
                v += __shfl_xor_sync(0xffffffffu, v, 2);
                s[rv][p] = 2.0f * rsqrtf(8.0f * v);
            }

#pragma unroll
        for (int rv = 0; rv < 2; rv++) {
            const int grow = mBase + warpM * 32 + mi * 16 + g + 8 * rv;
#pragma unroll
            for (int nj = 0; nj < 8; nj++) {
                const int p   = (nj & 3) >> 1;
                const int col = n0 + (nj & 3) * 8 + 2 * t4;
                float sc = s[rv][p];
                float v0 = d[mi][nj][rv * 2 + 0] * sc;
                float v1 = d[mi][nj][rv * 2 + 1] * sc;
                float* C = (nj < 4) ? Cr : Ci;
                *reinterpret_cast<float2*>(&C[(size_t)grow * DDIM + col]) =
                    make_float2(v0, v1);
            }
        }
    }
}

// ---------------------------------------------------------------------------
// theta SGEMM: cs/sn = cos/sin(x @ W_A^T + b_A). SIMT, 64 CTAs x 256 thr.
// ---------------------------------------------------------------------------
template <int BM, int BN, int BK, int TM, int TN>
__global__ __launch_bounds__((BM / TM) * (BN / TN))
void theta_kernel(const float* __restrict__ A,
                  const float* __restrict__ W, const float* __restrict__ bias,
                  float* __restrict__ Ccs, float* __restrict__ Csn)
{
    constexpr int NTH = (BM / TM) * (BN / TN);
    __shared__ float As[BK][BM + 4];
    __shared__ float Bs[BK][BN + 4];

    const int tid  = threadIdx.x;
    const int tcol = tid % (BN / TN);
    const int trow = tid / (BN / TN);
    const int mBase = blockIdx.x * BM;

    float acc[TM][TN];
#pragma unroll
    for (int i = 0; i < TM; i++)
#pragma unroll
        for (int j = 0; j < TN; j++) acc[i][j] = 0.0f;

    for (int k0 = 0; k0 < FEAT; k0 += BK) {
        for (int i = tid; i < BM * BK / 4; i += NTH) {
            int r  = i / (BK / 4);
            int kc = (i % (BK / 4)) * 4;
            float4 v = *reinterpret_cast<const float4*>(
                &A[(size_t)(mBase + r) * FEAT + k0 + kc]);
            As[kc + 0][r] = v.x; As[kc + 1][r] = v.y;
            As[kc + 2][r] = v.z; As[kc + 3][r] = v.w;
        }
        for (int i = tid; i < BN * BK / 4; i += NTH) {
            int r  = i / (BK / 4);
            int kc = (i % (BK / 4)) * 4;
            float4 v = *reinterpret_cast<const float4*>(
                &W[(size_t)r * FEAT + k0 + kc]);
            Bs[kc + 0][r] = v.x; Bs[kc + 1][r] = v.y;
            Bs[kc + 2][r] = v.z; Bs[kc + 3][r] = v.w;
        }
        __syncthreads();

#pragma unroll
        for (int k = 0; k < BK; k++) {
            float am[TM], bn[TN];
#pragma unroll
            for (int i = 0; i < TM; i++) am[i] = As[k][trow * TM + i];
#pragma unroll
            for (int j = 0; j < TN; j++) bn[j] = Bs[k][tcol * TN + j];
#pragma unroll
            for (int i = 0; i < TM; i++)
#pragma unroll
                for (int j = 0; j < TN; j++) acc[i][j] += am[i] * bn[j];
        }
        __syncthreads();
    }

    const int col = tcol * TN;
#pragma unroll
    for (int i = 0; i < TM; i++) {
        int row = mBase + trow * TM + i;
#pragma unroll
        for (int j = 0; j < TN; j++) {
            float th = acc[i][j] + bias[col + j];
            float s, c;
            sincosf(th, &s, &c);
            Ccs[(size_t)row * NT + col + j] = c;
            Csn[(size_t)row * NT + col + j] = s;
        }
    }
}

// ---------------------------------------------------------------------------
// A_real / A_imag zeros + diag fill (1 thread per float4 slot); tail = CSet.
// ---------------------------------------------------------------------------
__global__ __launch_bounds__(256)
void afill_kernel(const float* __restrict__ cs, const float* __restrict__ sn,
                  const float* __restrict__ csrc, float* __restrict__ out)
{
    int idx = blockIdx.x * blockDim.x + threadIdx.x;
    if (idx < BATCH * NT * 16) {
        int q = idx & 15;
        int t = (idx >> 4) & 63;
        int b = idx >> 10;

        float4 zr = make_float4(0.f, 0.f, 0.f, 0.f);
        float4 zi = make_float4(0.f, 0.f, 0.f, 0.f);
        if (q == (t >> 2)) {
            reinterpret_cast<float*>(&zr)[t & 3] = cs[b * NT + t];
            reinterpret_cast<float*>(&zi)[t & 3] = sn[b * NT + t];
        }
        reinterpret_cast<float4*>(out + OFF_AR)[idx] = zr;
        reinterpret_cast<float4*>(out + OFF_AI)[idx] = zi;
    } else {
        int c = idx - BATCH * NT * 16;
        if (c < CSETN * NT) {
            reinterpret_cast<float4*>(out + OFF_CS)[c] =
                reinterpret_cast<const float4*>(csrc)[c];
        }
    }
}

extern "C" void kernel_launch(void* const* d_in, const int* in_sizes, int n_in,
                              void* d_out, int out_size)
{
    const float* x    = (const float*)d_in[0];
    const float* W_A  = (const float*)d_in[1];
    const float* b_A  = (const float*)d_in[2];
    const float* W_Dr = (const float*)d_in[3];
    const float* b_Dr = (const float*)d_in[4];
    const float* W_Di = (const float*)d_in[5];
    const float* b_Di = (const float*)d_in[6];
    const float* CSet = (const float*)d_in[7];
    float* out = (float*)d_out;

    float *cs = nullptr, *sn = nullptr;
    cudaGetSymbolAddress((void**)&cs, g_cs);
    cudaGetSymbolAddress((void**)&sn, g_sn);

    static cudaStream_t s2 = nullptr;
    static cudaEvent_t evFork = nullptr, evJoin = nullptr;
    static bool init_tried = false;
    if (!init_tried) {
        init_tried = true;
        if (cudaStreamCreateWithFlags(&s2, cudaStreamNonBlocking) != cudaSuccess)
            s2 = nullptr;
        if (s2) {
            if (cudaEventCreateWithFlags(&evFork, cudaEventDisableTiming) != cudaSuccess ||
                cudaEventCreateWithFlags(&evJoin, cudaEventDisableTiming) != cudaSuccess) {
                evFork = evJoin = nullptr;
            }
        }
    }
    const bool forked = (s2 && evFork && evJoin);

    if (forked) {
        cudaEventRecord(evFork, 0);
        cudaStreamWaitEvent(s2, evFork, 0);
    }

    // Branch A (default stream): D GEMM + fused normalization
    dgemm_kernel<<<256, 128>>>(x, W_Dr, b_Dr, W_Di, b_Di, out);

    // Branch B: theta (cos/sin, grid 64) -> A planes + CSet
    {
        cudaStream_t sb = forked ? s2 : (cudaStream_t)0;
        theta_kernel<16, 64, 16, 1, 4><<<BATCH / 16, 256, 0, sb>>>(
            x, W_A, b_A, cs, sn);
        int total = BATCH * NT * 16 + CSETN * NT;
        afill_kernel<<<(total + 255) / 256, 256, 0, sb>>>(cs, sn, CSet, out);
        if (forked) {
            cudaEventRecord(evJoin, s2);
            cudaStreamWaitEvent(0, evJoin, 0);
        }
    }
}

// round 17
// speedup vs baseline: 1.3702x; 1.0006x over previous
#include <cuda_runtime.h>
#include <math.h>
#include <stdint.h>

#define BATCH 1024
#define FEAT  512
#define NT    64
#define CSETN 64
#define DDIM  1024

// Output layout (floats): A_real, A_imag, D_real_n, D_imag_n, CSet
#define OFF_AR 0L
#define OFF_AI 4194304L
#define OFF_DR 8388608L
#define OFF_DI 9437184L
#define OFF_CS 10485760L

__device__ float g_cs[BATCH * NT];
__device__ float g_sn[BATCH * NT];

__device__ __forceinline__ uint32_t f2tf32(float f) {
    uint32_t r;
    asm("cvt.rna.tf32.f32 %0, %1;" : "=r"(r) : "f"(f));
    return r;
}

__device__ __forceinline__ void mma_tf32(float* d, const uint32_t* a, const uint32_t* b) {
    asm volatile(
        "mma.sync.aligned.m16n8k8.row.col.f32.tf32.tf32.f32 "
        "{%0,%1,%2,%3}, {%4,%5,%6,%7}, {%8,%9}, {%0,%1,%2,%3};"
        : "+f"(d[0]), "+f"(d[1]), "+f"(d[2]), "+f"(d[3])
        : "r"(a[0]), "r"(a[1]), "r"(a[2]), "r"(a[3]), "r"(b[0]), "r"(b[1]));
}

// ---------------------------------------------------------------------------
// Fused tf32 GEMM + normalization + A-plane fill. 256 CTAs x 128 threads.
// Mainloop = exact R10 config (best measured): CTA 128 rows x (32 Dr + 32 Di
// cols as 64 B smem rows), 4 warps, warp tile 32 rows x 64 B-rows,
// smem [m][k] LDK=20 (conflict-free fragment LDS).
// PROLOGUE: this CTA also writes A_real/A_imag slots for its 128 batch rows
// and antennas t in {2*nt, 2*nt+1} (zeros + diag cos/sin) — 128 KB of STG
// issued before the mainloop so DRAM drains under the 30us of compute.
// CTA 0 additionally copies CSet.
// ---------------------------------------------------------------------------
__global__ __launch_bounds__(128, 3)
void dgemm_kernel(const float* __restrict__ x,
                  const float* __restrict__ Wr, const float* __restrict__ br,
                  const float* __restrict__ Wi, const float* __restrict__ bi,
                  const float* __restrict__ cs, const float* __restrict__ sn,
                  const float* __restrict__ csrc,
                  float* __restrict__ out)
{
    constexpr int LDK = 20;
    constexpr int BK  = 16;
    constexpr int NKT = FEAT / BK;   // 32

    __shared__ uint32_t As[2][128 * LDK];
    __shared__ uint32_t Bs[2][64 * LDK];

    const int tid   = threadIdx.x;
    const int lane  = tid & 31;
    const int warp  = tid >> 5;
    const int g     = lane >> 2;
    const int t4    = lane & 3;
    const int bx    = blockIdx.x;

    const int mBase = (bx >> 5) * 128;
    const int n0    = (bx & 31) * 32;

    float* Cr = out + OFF_DR;
    float* Ci = out + OFF_DI;

    // ================= A-plane prologue (fire-and-forget STG) =============
    {
        const int nt    = bx & 31;
        const int t     = 2 * nt + (lane >> 4);   // antenna for this lane
        const int q     = lane & 15;              // float4 col-chunk
        const bool diag = (q == (t >> 2));
        const int comp  = t & 3;
        const int plane = warp >> 1;              // 0 = real, 1 = imag
        const float* src = plane ? sn : cs;
        float* dst = out + (plane ? OFF_AI : OFF_AR);
        // warp-contiguous 512B stores: lanes cover f4 slots t*16+q
        const size_t fbase = (size_t)t * 64 + q * 4;
#pragma unroll 16
        for (int i = 0; i < 64; i++) {
            const int row = mBase + (warp & 1) * 64 + i;
            float4 v = make_float4(0.f, 0.f, 0.f, 0.f);
            if (diag) reinterpret_cast<float*>(&v)[comp] = src[(row << 6) + t];
            *reinterpret_cast<float4*>(dst + ((size_t)row << 12) + fbase) = v;
        }
        if (bx == 0) {
            const float4* c4 = reinterpret_cast<const float4*>(csrc);
            float4* d4 = reinterpret_cast<float4*>(out + OFF_CS);
#pragma unroll
            for (int i = 0; i < 32; i++)
                d4[tid + 128 * i] = c4[tid + 128 * i];
        }
    }

    // ================= GEMM mainloop (exact R10) ==========================
    float d[2][8][4];
#pragma unroll
    for (int i = 0; i < 2; i++)
#pragma unroll
        for (int j = 0; j < 8; j++)
#pragma unroll
            for (int v = 0; v < 4; v++) d[i][j][v] = 0.0f;

    float4 pa[4], pb[2];
    int arow[4], akq[4], brow[2], bkq[2];
#pragma unroll
    for (int t = 0; t < 4; t++) {
        int ti = tid + 128 * t;
        arow[t] = ti >> 2; akq[t] = ti & 3;
    }
#pragma unroll
    for (int t = 0; t < 2; t++) {
        int ti = tid + 128 * t;
        brow[t] = ti >> 2; bkq[t] = ti & 3;
    }

#define LOADG(kt)                                                              \
    do {                                                                       \
        _Pragma("unroll")                                                      \
        for (int t = 0; t < 4; t++)                                            \
            pa[t] = *reinterpret_cast<const float4*>(                          \
                &x[(size_t)(mBase + arow[t]) * FEAT + (kt) * BK + akq[t] * 4]); \
        _Pragma("unroll")                                                      \
        for (int t = 0; t < 2; t++) {                                          \
            const float* src = (brow[t] < 32)                                  \
                ? &Wr[(size_t)(n0 + brow[t]) * FEAT]                           \
                : &Wi[(size_t)(n0 + brow[t] - 32) * FEAT];                     \
            pb[t] = *reinterpret_cast<const float4*>(                          \
                &src[(kt) * BK + bkq[t] * 4]);                                 \
        }                                                                      \
    } while (0)

#define STS(bf)                                                                \
    do {                                                                       \
        _Pragma("unroll")                                                      \
        for (int t = 0; t < 4; t++)                                            \
            *reinterpret_cast<uint4*>(&As[bf][arow[t] * LDK + akq[t] * 4]) =   \
                make_uint4(f2tf32(pa[t].x), f2tf32(pa[t].y),                   \
                           f2tf32(pa[t].z), f2tf32(pa[t].w));                  \
        _Pragma("unroll")                                                      \
        for (int t = 0; t < 2; t++)                                            \
            *reinterpret_cast<uint4*>(&Bs[bf][brow[t] * LDK + bkq[t] * 4]) =   \
                make_uint4(f2tf32(pb[t].x), f2tf32(pb[t].y),                   \
                           f2tf32(pb[t].z), f2tf32(pb[t].w));                  \
    } while (0)

    LOADG(0);
    STS(0);
    __syncthreads();

    int buf = 0;
    for (int kt = 0; kt < NKT; kt++) {
        if (kt < NKT - 1) LOADG(kt + 1);

        const uint32_t* as = As[buf];
        const uint32_t* bs = Bs[buf];
#pragma unroll
        for (int ks = 0; ks < 2; ks++) {
            const int kb = ks * 8 + t4;
            uint32_t af[2][4];
#pragma unroll
            for (int mi = 0; mi < 2; mi++) {
                const int r0 = (warp * 32 + mi * 16 + g) * LDK;
                af[mi][0] = as[r0 + kb];
                af[mi][1] = as[r0 + 8 * LDK + kb];
                af[mi][2] = as[r0 + kb + 4];
                af[mi][3] = as[r0 + 8 * LDK + kb + 4];
            }
            uint32_t bq[8][2];
#pragma unroll
            for (int nj = 0; nj < 8; nj++) {
                const int rb = (nj * 8 + g) * LDK;
                bq[nj][0] = bs[rb + kb];
                bq[nj][1] = bs[rb + kb + 4];
            }
#pragma unroll
            for (int mi = 0; mi < 2; mi++)
#pragma unroll
                for (int nj = 0; nj < 8; nj++)
                    mma_tf32(d[mi][nj], af[mi], bq[nj]);
        }

        if (kt < NKT - 1) {
            STS(buf ^ 1);
            __syncthreads();
            buf ^= 1;
        }
    }
#undef LOADG
#undef STS

    // ---------- Epilogue: bias + warp-local normalization (R10) ----------
#pragma unroll
    for (int nj = 0; nj < 8; nj++) {
        const int col = n0 + (nj & 3) * 8 + 2 * t4;
        const float* bsrc = (nj < 4) ? br : bi;
        float bxv = bsrc[col];
        float byv = bsrc[col + 1];
#pragma unroll
        for (int mi = 0; mi < 2; mi++) {
            d[mi][nj][0] += bxv; d[mi][nj][1] += byv;
            d[mi][nj][2] += bxv; d[mi][nj][3] += byv;
        }
    }

#pragma unroll
    for (int mi = 0; mi < 2; mi++) {
        float s[2][2];
#pragma unroll
        for (int rv = 0; rv < 2; rv++)
#pragma unroll
            for (int p = 0; p < 2; p++) s[rv][p] = 0.0f;

#pragma unroll
        for (int nj = 0; nj < 8; nj++) {
            int p = (nj & 3) >> 1;
            s[0][p] += d[mi][nj][0] * d[mi][nj][0] + d[mi][nj][1] * d[mi][nj][1];
            s[1][p] += d[mi][nj][2] * d[mi][nj][2] + d[mi][nj][3] * d[mi][nj][3];
        }
#pragma unroll
        for (int rv = 0; rv < 2; rv++)
#pragma unroll
            for (int p = 0; p < 2; p++) {
                float v = s[rv][p];
                v += __shfl_xor_sync(0xffffffffu, v, 1);
                v += __shfl_xor_sync(0xffffffffu, v, 2);
                s[rv][p] = 2.0f * rsqrtf(8.0f * v);
            }

#pragma unroll
        for (int rv = 0; rv < 2; rv++) {
            const int grow = mBase + warp * 32 + mi * 16 + g + 8 * rv;
#pragma unroll
            for (int nj = 0; nj < 8; nj++) {
                const int p   = (nj & 3) >> 1;
                const int col = n0 + (nj & 3) * 8 + 2 * t4;
                float sc = s[rv][p];
                float v0 = d[mi][nj][rv * 2 + 0] * sc;
                float v1 = d[mi][nj][rv * 2 + 1] * sc;
                float* C = (nj < 4) ? Cr : Ci;
                *reinterpret_cast<float2*>(&C[(size_t)grow * DDIM + col]) =
                    make_float2(v0, v1);
            }
        }
    }
}

// ---------------------------------------------------------------------------
// theta SGEMM: cs/sn = cos/sin(x @ W_A^T + b_A). SIMT, 64 CTAs x 256 thr.
// ---------------------------------------------------------------------------
template <int BM, int BN, int BK, int TM, int TN>
__global__ __launch_bounds__((BM / TM) * (BN / TN))
void theta_kernel(const float* __restrict__ A,
                  const float* __restrict__ W, const float* __restrict__ bias,
                  float* __restrict__ Ccs, float* __restrict__ Csn)
{
    constexpr int NTH = (BM / TM) * (BN / TN);
    __shared__ float As[BK][BM + 4];
    __shared__ float Bs[BK][BN + 4];

    const int tid  = threadIdx.x;
    const int tcol = tid % (BN / TN);
    const int trow = tid / (BN / TN);
    const int mBase = blockIdx.x * BM;

    float acc[TM][TN];
#pragma unroll
    for (int i = 0; i < TM; i++)
#pragma unroll
        for (int j = 0; j < TN; j++) acc[i][j] = 0.0f;

    for (int k0 = 0; k0 < FEAT; k0 += BK) {
        for (int i = tid; i < BM * BK / 4; i += NTH) {
            int r  = i / (BK / 4);
            int kc = (i % (BK / 4)) * 4;
            float4 v = *reinterpret_cast<const float4*>(
                &A[(size_t)(mBase + r) * FEAT + k0 + kc]);
            As[kc + 0][r] = v.x; As[kc + 1][r] = v.y;
            As[kc + 2][r] = v.z; As[kc + 3][r] = v.w;
        }
        for (int i = tid; i < BN * BK / 4; i += NTH) {
            int r  = i / (BK / 4);
            int kc = (i % (BK / 4)) * 4;
            float4 v = *reinterpret_cast<const float4*>(
                &W[(size_t)r * FEAT + k0 + kc]);
            Bs[kc + 0][r] = v.x; Bs[kc + 1][r] = v.y;
            Bs[kc + 2][r] = v.z; Bs[kc + 3][r] = v.w;
        }
        __syncthreads();

#pragma unroll
        for (int k = 0; k < BK; k++) {
            float am[TM], bn[TN];
#pragma unroll
            for (int i = 0; i < TM; i++) am[i] = As[k][trow * TM + i];
#pragma unroll
            for (int j = 0; j < TN; j++) bn[j] = Bs[k][tcol * TN + j];
#pragma unroll
            for (int i = 0; i < TM; i++)
#pragma unroll
                for (int j = 0; j < TN; j++) acc[i][j] += am[i] * bn[j];
        }
        __syncthreads();
    }

    const int col = tcol * TN;
#pragma unroll
    for (int i = 0; i < TM; i++) {
        int row = mBase + trow * TM + i;
#pragma unroll
        for (int j = 0; j < TN; j++) {
            float th = acc[i][j] + bias[col + j];
            float s, c;
            sincosf(th, &s, &c);
            Ccs[(size_t)row * NT + col + j] = c;
            Csn[(size_t)row * NT + col + j] = s;
        }
    }
}

extern "C" void kernel_launch(void* const* d_in, const int* in_sizes, int n_in,
                              void* d_out, int out_size)
{
    const float* x    = (const float*)d_in[0];
    const float* W_A  = (const float*)d_in[1];
    const float* b_A  = (const float*)d_in[2];
    const float* W_Dr = (const float*)d_in[3];
    const float* b_Dr = (const float*)d_in[4];
    const float* W_Di = (const float*)d_in[5];
    const float* b_Di = (const float*)d_in[6];
    const float* CSet = (const float*)d_in[7];
    float* out = (float*)d_out;

    float *cs = nullptr, *sn = nullptr;
    cudaGetSymbolAddress((void**)&cs, g_cs);
    cudaGetSymbolAddress((void**)&sn, g_sn);

    // theta first (3us), then the fused GEMM+norm+A-fill (A stores drain
    // under the GEMM mainloop).
    theta_kernel<16, 64, 16, 1, 4><<<BATCH / 16, 256>>>(x, W_A, b_A, cs, sn);
    dgemm_kernel<<<256, 128>>>(x, W_Dr, b_Dr, W_Di, b_Di, cs, sn, CSet, out);
}